// round 13
// baseline (speedup 1.0000x reference)
#include <cuda_runtime.h>
#include <cuda_fp16.h>
#include <math.h>
#include <stdint.h>

#define T_TOK   1024
#define DMODEL  768
#define NEXP    16
#define FFN     3072
#define TOPK    4
#define NASSIGN (T_TOK*TOPK)

// ---------------- scratch (device globals; no allocations allowed) ----------
__device__ uint16_t g_Xg_h[(size_t)NASSIGN*DMODEL];   // gathered activations, fp16
__device__ uint16_t g_act_h[(size_t)NASSIGN*FFN];     // silu(gate)*up, fp16
__device__ float    g_down[2][(size_t)NASSIGN*DMODEL];// down-proj partial rows (split-K)
__device__ int      g_topk_idx[T_TOK*TOPK];
__device__ float    g_topk_w[T_TOK*TOPK];
__device__ int      g_off[NEXP+1];
__device__ int      g_assign_token[NASSIGN];
__device__ int      g_token_pos[T_TOK*TOPK];

// ================= helpers =================
__device__ __forceinline__ uint32_t smem_u32(const void* p) {
    uint32_t a;
    asm("{ .reg .u64 t; cvta.to.shared.u64 t, %1; cvt.u32.u64 %0, t; }" : "=r"(a) : "l"(p));
    return a;
}
__device__ __forceinline__ uint32_t pack_h2(float x, float y) {
    uint32_t h;
    asm("cvt.rn.f16x2.f32 %0, %1, %2;" : "=r"(h) : "f"(y), "f"(x));
    return h;
}

#define LDSM_X4(r, addr) \
    asm volatile("ldmatrix.sync.aligned.m8n8.x4.shared.b16 {%0,%1,%2,%3}, [%4];" \
        : "=r"((r)[0]),"=r"((r)[1]),"=r"((r)[2]),"=r"((r)[3]) : "r"(addr))

#define MMA_F16(d, a, b0, b1) \
    asm volatile("mma.sync.aligned.m16n8k16.row.col.f32.f16.f16.f32 " \
        "{%0,%1,%2,%3},{%4,%5,%6,%7},{%8,%9},{%0,%1,%2,%3};" \
        : "+f"((d)[0]),"+f"((d)[1]),"+f"((d)[2]),"+f"((d)[3]) \
        : "r"((a)[0]),"r"((a)[1]),"r"((a)[2]),"r"((a)[3]),"r"(b0),"r"(b1))

#define CPA16(dst, src, sz) \
    asm volatile("cp.async.cg.shared.global [%0], [%1], 16, %2;" :: "r"(dst), "l"(src), "r"(sz) : "memory")
#define CP_COMMIT() asm volatile("cp.async.commit_group;" ::: "memory")
#define CP_WAIT1()  asm volatile("cp.async.wait_group 1;" ::: "memory")

// ---------------- router: logits -> softmax -> top4 -> renorm ---------------
__global__ void moe_router(const float* __restrict__ x, const float* __restrict__ rw) {
    const int t = blockIdx.x;
    __shared__ float sx[DMODEL];
    __shared__ float slog[NEXP];
    const int tid = threadIdx.x;
    const float4* xr = (const float4*)(x + (size_t)t*DMODEL);
    float4* sx4 = (float4*)sx;
    for (int i = tid; i < DMODEL/4; i += 128) sx4[i] = xr[i];
    __syncthreads();

    const int warp = tid >> 5, lane = tid & 31;
    for (int e = warp; e < NEXP; e += 4) {
        const float* w = rw + (size_t)e*DMODEL;
        float s = 0.f;
        for (int k = lane; k < DMODEL; k += 32) s = fmaf(sx[k], w[k], s);
        #pragma unroll
        for (int o = 16; o > 0; o >>= 1) s += __shfl_down_sync(0xffffffffu, s, o);
        if (lane == 0) slog[e] = s;
    }
    __syncthreads();

    if (tid == 0) {
        float m = -1e30f;
        #pragma unroll
        for (int e = 0; e < NEXP; e++) m = fmaxf(m, slog[e]);
        float p[NEXP]; float sum = 0.f;
        #pragma unroll
        for (int e = 0; e < NEXP; e++) { p[e] = __expf(slog[e]-m); sum += p[e]; }
        const float inv = 1.f/sum;
        #pragma unroll
        for (int e = 0; e < NEXP; e++) p[e] *= inv;

        int idx[TOPK]; float wv[TOPK]; float ws = 0.f;
        #pragma unroll
        for (int s2 = 0; s2 < TOPK; s2++) {
            int bi = 0; float bv = -1.f;
            #pragma unroll
            for (int e = 0; e < NEXP; e++) if (p[e] > bv) { bv = p[e]; bi = e; }
            idx[s2] = bi; wv[s2] = bv; ws += bv; p[bi] = -2.f;
        }
        const float invw = 1.f/ws;
        #pragma unroll
        for (int s2 = 0; s2 < TOPK; s2++) {
            g_topk_idx[t*TOPK+s2] = idx[s2];
            g_topk_w[t*TOPK+s2]   = wv[s2]*invw;
        }
    }
}

// ---------------- setup: count + prefix + scatter, one block -----------------
__global__ void moe_setup() {
    __shared__ int sc[NEXP], sf[NEXP], so[NEXP];
    const int tid = threadIdx.x;      // 1024 threads, one per token
    if (tid < NEXP) { sc[tid] = 0; sf[tid] = 0; }
    __syncthreads();
    int es[TOPK];
    #pragma unroll
    for (int s = 0; s < TOPK; s++) {
        es[s] = g_topk_idx[tid*TOPK + s];
        atomicAdd(&sc[es[s]], 1);
    }
    __syncthreads();
    if (tid == 0) {
        int s = 0;
        #pragma unroll
        for (int e = 0; e < NEXP; e++) { so[e] = s; g_off[e] = s; s += sc[e]; }
        g_off[NEXP] = s;
    }
    __syncthreads();
    #pragma unroll
    for (int s = 0; s < TOPK; s++) {
        int e = es[s];
        int p = so[e] + atomicAdd(&sf[e], 1);
        g_assign_token[p]     = tid;
        g_token_pos[tid*TOPK+s] = p;
    }
}

// ---------------- gather + convert to fp16 ----------------------------------
__global__ void moe_gather(const float* __restrict__ x) {
    int id = blockIdx.x*blockDim.x + threadIdx.x;
    int p = id / (DMODEL/4);
    int q = id % (DMODEL/4);
    int t = g_assign_token[p];
    float4 v = ((const float4*)x)[(size_t)t*(DMODEL/4) + q];
    uint2 h;
    h.x = pack_h2(v.x, v.y);
    h.y = pack_h2(v.z, v.w);
    *(uint2*)(g_Xg_h + (size_t)p*DMODEL + q*4) = h;
}

// ===================== GEMM1 (fp16 mma, 3-stage + frag pipeline) =============
// BM=128, B tile = 128 smem rows (64 W1 + 64 V1 interleaved by 16), BK=32.
// SMEM row: 32 fp16 = 64B data + 16B pad = 80B. Stage: A 10240 | B 10240.
// 3 stages = 61440 dynamic; 2 CTAs/SM.
#define G1_STAGE 20480
#define G1_NCH   (DMODEL/32)   // 24

__global__ __launch_bounds__(256, 2) void moe_gemm1_mma(const float* __restrict__ w1,
                                                        const float* __restrict__ v1) {
    const int e    = blockIdx.z;
    const int base = g_off[e];
    const int cnt  = g_off[e+1] - base;
    const int m0   = blockIdx.y * 128;
    if (m0 >= cnt) return;
    const int n0w  = blockIdx.x * 64;

    extern __shared__ char smem[];
    const uint32_t smb = smem_u32(smem);

    const int tid = threadIdx.x, lane = tid & 31, wid = tid >> 5;
    const int wm = wid >> 2, wn = wid & 3;     // 2 x 4 warp grid; warp tile 64x32

    // ---- A via cp.async (fp16) ----
    const int crow  = tid >> 1;                 // 0..127
    const int cpair = tid & 1;
    const uint32_t asz = ((m0 + crow) < cnt) ? 16u : 0u;
    const uint16_t* aH = g_Xg_h + (size_t)(base + m0 + crow)*DMODEL + cpair*16;
    const uint32_t adst = smb + (uint32_t)crow*80 + cpair*32;

    // ---- B: fp32 LDG + fp16 cvt + STS (rows 0-63 W1, 64-127 V1 by 16) ----
    const int brow  = tid >> 1;
    const int bhalf = tid & 1;
    const int grp   = brow >> 5, wi = brow & 31;
    const float* bsrc = (wi < 16)
        ? (w1 + (size_t)e*FFN*DMODEL + (size_t)(n0w + grp*16 + wi)*DMODEL)
        : (v1 + (size_t)e*FFN*DMODEL + (size_t)(n0w + grp*16 + (wi-16))*DMODEL);
    const float* bptr = bsrc + bhalf*16;
    const uint32_t boff = (uint32_t)brow*80 + bhalf*32;

    const int rl = (lane & 7) + ((lane >> 3) & 1) * 8;
    const int kl = (lane >> 4) * 16;

    float acc[4][4][4];
    #pragma unroll
    for (int i = 0; i < 4; i++)
        #pragma unroll
        for (int j = 0; j < 4; j++)
            #pragma unroll
            for (int r = 0; r < 4; r++) acc[i][j][r] = 0.f;

    float4 b4[4];

    #define G1_CPA(c) do { \
        if ((c) < G1_NCH) { \
            const uint32_t d = adst + ((c)%3)*G1_STAGE; \
            CPA16(d,      aH + (size_t)(c)*32,     asz); \
            CPA16(d + 16, aH + (size_t)(c)*32 + 8, asz); \
        } \
        CP_COMMIT(); \
    } while (0)

    #define G1_LDGB(c) do { \
        const float4* bp = (const float4*)(bptr + (size_t)(c)*32); \
        b4[0]=bp[0]; b4[1]=bp[1]; b4[2]=bp[2]; b4[3]=bp[3]; \
    } while (0)

    #define G1_STSB(c) do { \
        char* s_ = smem + ((c)%3)*G1_STAGE + 10240; \
        uint4 h; \
        h.x = pack_h2(b4[0].x, b4[0].y); h.y = pack_h2(b4[0].z, b4[0].w); \
        h.z = pack_h2(b4[1].x, b4[1].y); h.w = pack_h2(b4[1].z, b4[1].w); \
        *(uint4*)(s_ + boff) = h; \
        h.x = pack_h2(b4[2].x, b4[2].y); h.y = pack_h2(b4[2].z, b4[2].w); \
        h.z = pack_h2(b4[3].x, b4[3].y); h.w = pack_h2(b4[3].z, b4[3].w); \
        *(uint4*)(s_ + boff + 16) = h; \
    } while (0)

    // ---- prologue ----
    G1_CPA(0);                 // group -> chunk 0
    G1_CPA(1);                 // group -> chunk 1
    G1_LDGB(0);  G1_STSB(0);   // B0 -> stage 0
    G1_LDGB(1);                // b4 = B1
    CP_WAIT1();                // A0 landed (A1 may be in flight)
    __syncthreads();

    for (int c = 0; c < G1_NCH; c++) {
        const uint32_t sA = smb + (c%3)*G1_STAGE;
        const uint32_t sB = sA + 10240;
        G1_CPA(c + 2);         // prefetch A two chunks ahead

        uint32_t bh[2][4];
        uint32_t ah[2][4];

        #pragma unroll
        for (int s16 = 0; s16 < 2; s16++) {
            const int kb = s16*32 + kl;
            // B frags for this s16
            #pragma unroll
            for (int jt = 0; jt < 2; jt++) {
                const uint32_t ba = (uint32_t)(wn*32 + jt*16 + rl)*80 + kb;
                LDSM_X4(bh[jt], sB + ba);
            }
            // A frag pipeline across i
            LDSM_X4(ah[0], sA + (uint32_t)(wm*64 + rl)*80 + kb);
            #pragma unroll
            for (int i = 0; i < 4; i++) {
                const int p = i & 1;
                if (i < 3)
                    LDSM_X4(ah[p ^ 1], sA + (uint32_t)(wm*64 + (i+1)*16 + rl)*80 + kb);
                #pragma unroll
                for (int jn = 0; jn < 4; jn++) {
                    const int jt = jn >> 1, hf = jn & 1;
                    MMA_F16(acc[i][jn], ah[p], bh[jt][hf], bh[jt][hf+2]);
                }
                if (s16 == 0) {
                    if (i == 1 && (c + 1 < G1_NCH)) G1_STSB(c + 1);
                    if (i == 2 && (c + 2 < G1_NCH)) G1_LDGB(c + 2);
                }
            }
        }

        if (c + 1 < G1_NCH) {
            CP_WAIT1();        // A(c+1) landed; A(c+2) may be in flight
            __syncthreads();
        }
    }

    // ---- epilogue: silu(gate)*up -> fp16 ----
    const int r0 = lane >> 2;
    const int cq = (lane & 3) * 2;
    #pragma unroll
    for (int i = 0; i < 4; i++) {
        const int mb = m0 + wm*64 + i*16;
        #pragma unroll
        for (int rg = 0; rg < 2; rg++) {
            const int m = mb + rg*8 + r0;
            if (m < cnt) {
                const size_t rowb = (size_t)(base + m)*FFN;
                #pragma unroll
                for (int jj = 0; jj < 2; jj++) {
                    const int cc = n0w + wn*16 + jj*8 + cq;
                    float g0 = acc[i][jj][rg*2+0], g1 = acc[i][jj][rg*2+1];
                    float u0 = acc[i][jj+2][rg*2+0], u1 = acc[i][jj+2][rg*2+1];
                    float o0 = g0/(1.f+__expf(-g0))*u0;
                    float o1 = g1/(1.f+__expf(-g1))*u1;
                    *(uint32_t*)(g_act_h + rowb + cc) = pack_h2(o0, o1);
                }
            }
        }
    }
    #undef G1_CPA
    #undef G1_LDGB
    #undef G1_STSB
}

// ===================== GEMM2 (fp16 mma, BN=128, split-K x2) ==================
// BM=128, BN=128 (128 W2 rows), BK=32, K split in 2 halves of 1536.
// Stage: A 10240 | B 10240 = 20480; 3 stages = 61440; 2 CTAs/SM.
#define G2_STAGE 20480
#define G2_NCH   (FFN/64)   // 48 chunks per K-half
#define G2_NX    (DMODEL/128)  // 6 n-blocks

__global__ __launch_bounds__(256, 2) void moe_gemm2_mma(const float* __restrict__ w2) {
    const int e    = blockIdx.z;
    const int base = g_off[e];
    const int cnt  = g_off[e+1] - base;
    const int m0   = blockIdx.y * 128;
    if (m0 >= cnt) return;
    const int n0   = (blockIdx.x % G2_NX) * 128;
    const int kh   = blockIdx.x / G2_NX;           // K-half: 0 or 1
    const int koff = kh * (FFN/2);                 // 1536 elements

    extern __shared__ char smem[];
    const uint32_t smb = smem_u32(smem);

    const int tid = threadIdx.x, lane = tid & 31, wid = tid >> 5;
    const int wm = wid >> 2, wn = wid & 3;     // 2 x 4 warp grid; warp tile 64x32

    // ---- A via cp.async (fp16 act) ----
    const int crow  = tid >> 1;
    const int cpair = tid & 1;
    const uint32_t asz = ((m0 + crow) < cnt) ? 16u : 0u;
    const uint16_t* aH = g_act_h + (size_t)(base + m0 + crow)*FFN + koff + cpair*16;
    const uint32_t adst = smb + (uint32_t)crow*80 + cpair*32;

    // ---- B: 128 W2 rows, 2 threads per row ----
    const int brow  = tid >> 1;                 // 0..127
    const int bhalf = tid & 1;
    const float* bptr = w2 + (size_t)e*DMODEL*FFN + (size_t)(n0 + brow)*FFN + koff + bhalf*16;
    const uint32_t boff = (uint32_t)brow*80 + bhalf*32;

    const int rl = (lane & 7) + ((lane >> 3) & 1) * 8;
    const int kl = (lane >> 4) * 16;

    float acc[4][4][4];
    #pragma unroll
    for (int i = 0; i < 4; i++)
        #pragma unroll
        for (int j = 0; j < 4; j++)
            #pragma unroll
            for (int r = 0; r < 4; r++) acc[i][j][r] = 0.f;

    float4 b4[4];

    #define G2_CPA(c) do { \
        if ((c) < G2_NCH) { \
            const uint32_t d = adst + ((c)%3)*G2_STAGE; \
            CPA16(d,      aH + (size_t)(c)*32,     asz); \
            CPA16(d + 16, aH + (size_t)(c)*32 + 8, asz); \
        } \
        CP_COMMIT(); \
    } while (0)

    #define G2_LDGB(c) do { \
        const float4* bp = (const float4*)(bptr + (size_t)(c)*32); \
        b4[0]=bp[0]; b4[1]=bp[1]; b4[2]=bp[2]; b4[3]=bp[3]; \
    } while (0)

    #define G2_STSB(c) do { \
        char* s_ = smem + ((c)%3)*G2_STAGE + 10240; \
        uint4 h; \
        h.x = pack_h2(b4[0].x, b4[0].y); h.y = pack_h2(b4[0].z, b4[0].w); \
        h.z = pack_h2(b4[1].x, b4[1].y); h.w = pack_h2(b4[1].z, b4[1].w); \
        *(uint4*)(s_ + boff) = h; \
        h.x = pack_h2(b4[2].x, b4[2].y); h.y = pack_h2(b4[2].z, b4[2].w); \
        h.z = pack_h2(b4[3].x, b4[3].y); h.w = pack_h2(b4[3].z, b4[3].w); \
        *(uint4*)(s_ + boff + 16) = h; \
    } while (0)

    // ---- prologue ----
    G2_CPA(0);
    G2_CPA(1);
    G2_LDGB(0);  G2_STSB(0);
    G2_LDGB(1);
    CP_WAIT1();
    __syncthreads();

    for (int c = 0; c < G2_NCH; c++) {
        const uint32_t sA = smb + (c%3)*G2_STAGE;
        const uint32_t sB = sA + 10240;
        G2_CPA(c + 2);

        uint32_t bh[2][4];
        uint32_t ah[2][4];

        #pragma unroll
        for (int s16 = 0; s16 < 2; s16++) {
            const int kb = s16*32 + kl;
            #pragma unroll
            for (int jt = 0; jt < 2; jt++) {
                const uint32_t ba = (uint32_t)(wn*32 + jt*16 + rl)*80 + kb;
                LDSM_X4(bh[jt], sB + ba);
            }
            LDSM_X4(ah[0], sA + (uint32_t)(wm*64 + rl)*80 + kb);
            #pragma unroll
            for (int i = 0; i < 4; i++) {
                const int p = i & 1;
                if (i < 3)
                    LDSM_X4(ah[p ^ 1], sA + (uint32_t)(wm*64 + (i+1)*16 + rl)*80 + kb);
                #pragma unroll
                for (int jn = 0; jn < 4; jn++) {
                    const int jt = jn >> 1, hf = jn & 1;
                    MMA_F16(acc[i][jn], ah[p], bh[jt][hf], bh[jt][hf+2]);
                }
                if (s16 == 0) {
                    if (i == 1 && (c + 1 < G2_NCH)) G2_STSB(c + 1);
                    if (i == 2 && (c + 2 < G2_NCH)) G2_LDGB(c + 2);
                }
            }
        }

        if (c + 1 < G2_NCH) {
            CP_WAIT1();
            __syncthreads();
        }
    }

    // ---- epilogue: fp32 partial rows of g_down[kh] ----
    float* dwn = g_down[kh];
    const int r0 = lane >> 2;
    const int cq = (lane & 3) * 2;
    #pragma unroll
    for (int i = 0; i < 4; i++) {
        const int mb = m0 + wm*64 + i*16;
        #pragma unroll
        for (int rg = 0; rg < 2; rg++) {
            const int m = mb + rg*8 + r0;
            if (m < cnt) {
                float* orow = dwn + (size_t)(base + m)*DMODEL;
                #pragma unroll
                for (int jn = 0; jn < 4; jn++) {
                    const int cc = n0 + wn*32 + jn*8 + cq;
                    float2 o = { acc[i][jn][rg*2+0], acc[i][jn][rg*2+1] };
                    *(float2*)(orow + cc) = o;
                }
            }
        }
    }
    #undef G2_CPA
    #undef G2_LDGB
    #undef G2_STSB
}

// ---------------- combine: out[t] = sum_slot w * (down0 + down1) -------------
__global__ void moe_combine(float* __restrict__ out) {
    int id = blockIdx.x*blockDim.x + threadIdx.x;
    int t = id / (DMODEL/4);
    int q = id % (DMODEL/4);
    float4 acc = make_float4(0,0,0,0);
    #pragma unroll
    for (int s = 0; s < TOPK; s++) {
        int   p = g_token_pos[t*TOPK+s];
        float w = g_topk_w[t*TOPK+s];
        float4 v0 = ((const float4*)g_down[0])[(size_t)p*(DMODEL/4) + q];
        float4 v1 = ((const float4*)g_down[1])[(size_t)p*(DMODEL/4) + q];
        acc.x = fmaf(w, v0.x + v1.x, acc.x);
        acc.y = fmaf(w, v0.y + v1.y, acc.y);
        acc.z = fmaf(w, v0.z + v1.z, acc.z);
        acc.w = fmaf(w, v0.w + v1.w, acc.w);
    }
    ((float4*)out)[id] = acc;
}

// ---------------- launch ----------------------------------------------------
extern "C" void kernel_launch(void* const* d_in, const int* in_sizes, int n_in,
                              void* d_out, int out_size) {
    const float* x  = (const float*)d_in[0];
    const float* rw = (const float*)d_in[1];
    const float* w1 = (const float*)d_in[2];
    const float* v1 = (const float*)d_in[3];
    const float* w2 = (const float*)d_in[4];
    float* out = (float*)d_out;

    cudaFuncSetAttribute(moe_gemm1_mma, cudaFuncAttributeMaxDynamicSharedMemorySize, 3*G1_STAGE);
    cudaFuncSetAttribute(moe_gemm2_mma, cudaFuncAttributeMaxDynamicSharedMemorySize, 3*G2_STAGE);

    moe_router<<<T_TOK, 128>>>(x, rw);                // launch 1
    moe_setup<<<1, 1024>>>();                         // launch 2
    moe_gather<<<(NASSIGN*(DMODEL/4))/256, 256>>>(x); // launch 3

    dim3 g1(FFN/64, NASSIGN/128, NEXP);               // launch 4 <- profiled slot
    moe_gemm1_mma<<<g1, 256, 3*G1_STAGE>>>(w1, v1);

    dim3 g2(2*G2_NX, NASSIGN/128, NEXP);              // 12 x 32 x 16 (n-block x K-half)
    moe_gemm2_mma<<<g2, 256, 3*G2_STAGE>>>(w2);

    moe_combine<<<(T_TOK*(DMODEL/4))/256, 256>>>(out);
}

// round 14
// speedup vs baseline: 1.0055x; 1.0055x over previous
#include <cuda_runtime.h>
#include <cuda_fp16.h>
#include <math.h>
#include <stdint.h>

#define T_TOK   1024
#define DMODEL  768
#define NEXP    16
#define FFN     3072
#define TOPK    4
#define NASSIGN (T_TOK*TOPK)

// ---------------- scratch (device globals; no allocations allowed) ----------
__device__ uint16_t g_Xg_h[(size_t)NASSIGN*DMODEL];   // gathered activations, fp16
__device__ uint16_t g_act_h[(size_t)NASSIGN*FFN];     // silu(gate)*up, fp16
__device__ uint16_t g_down_h[(size_t)NASSIGN*DMODEL]; // down-proj rows (fp16)
__device__ int      g_topk_idx[T_TOK*TOPK];
__device__ float    g_topk_w[T_TOK*TOPK];
__device__ int      g_off[NEXP+1];
__device__ int      g_assign_token[NASSIGN];
__device__ int      g_token_pos[T_TOK*TOPK];

// ================= helpers =================
__device__ __forceinline__ uint32_t smem_u32(const void* p) {
    uint32_t a;
    asm("{ .reg .u64 t; cvta.to.shared.u64 t, %1; cvt.u32.u64 %0, t; }" : "=r"(a) : "l"(p));
    return a;
}
__device__ __forceinline__ uint32_t pack_h2(float x, float y) {
    uint32_t h;
    asm("cvt.rn.f16x2.f32 %0, %1, %2;" : "=r"(h) : "f"(y), "f"(x));
    return h;
}
__device__ __forceinline__ float2 unpack_h2(uint32_t h) {
    float lo, hi;
    asm("{ .reg .b16 a, b;\n\t mov.b32 {a, b}, %2;\n\t cvt.f32.f16 %0, a;\n\t cvt.f32.f16 %1, b; }"
        : "=f"(lo), "=f"(hi) : "r"(h));
    return make_float2(lo, hi);
}

#define LDSM_X4(r, addr) \
    asm volatile("ldmatrix.sync.aligned.m8n8.x4.shared.b16 {%0,%1,%2,%3}, [%4];" \
        : "=r"((r)[0]),"=r"((r)[1]),"=r"((r)[2]),"=r"((r)[3]) : "r"(addr))

#define MMA_F16(d, a, b0, b1) \
    asm volatile("mma.sync.aligned.m16n8k16.row.col.f32.f16.f16.f32 " \
        "{%0,%1,%2,%3},{%4,%5,%6,%7},{%8,%9},{%0,%1,%2,%3};" \
        : "+f"((d)[0]),"+f"((d)[1]),"+f"((d)[2]),"+f"((d)[3]) \
        : "r"((a)[0]),"r"((a)[1]),"r"((a)[2]),"r"((a)[3]),"r"(b0),"r"(b1))

#define CPA16(dst, src, sz) \
    asm volatile("cp.async.cg.shared.global [%0], [%1], 16, %2;" :: "r"(dst), "l"(src), "r"(sz) : "memory")
#define CP_COMMIT() asm volatile("cp.async.commit_group;" ::: "memory")
#define CP_WAIT1()  asm volatile("cp.async.wait_group 1;" ::: "memory")

// ---------------- router: logits -> softmax -> top4 -> renorm ---------------
__global__ void moe_router(const float* __restrict__ x, const float* __restrict__ rw) {
    const int t = blockIdx.x;
    __shared__ float sx[DMODEL];
    __shared__ float slog[NEXP];
    const int tid = threadIdx.x;
    const float4* xr = (const float4*)(x + (size_t)t*DMODEL);
    float4* sx4 = (float4*)sx;
    for (int i = tid; i < DMODEL/4; i += 128) sx4[i] = xr[i];
    __syncthreads();

    const int warp = tid >> 5, lane = tid & 31;
    for (int e = warp; e < NEXP; e += 4) {
        const float* w = rw + (size_t)e*DMODEL;
        float s = 0.f;
        for (int k = lane; k < DMODEL; k += 32) s = fmaf(sx[k], w[k], s);
        #pragma unroll
        for (int o = 16; o > 0; o >>= 1) s += __shfl_down_sync(0xffffffffu, s, o);
        if (lane == 0) slog[e] = s;
    }
    __syncthreads();

    if (tid == 0) {
        float m = -1e30f;
        #pragma unroll
        for (int e = 0; e < NEXP; e++) m = fmaxf(m, slog[e]);
        float p[NEXP]; float sum = 0.f;
        #pragma unroll
        for (int e = 0; e < NEXP; e++) { p[e] = __expf(slog[e]-m); sum += p[e]; }
        const float inv = 1.f/sum;
        #pragma unroll
        for (int e = 0; e < NEXP; e++) p[e] *= inv;

        int idx[TOPK]; float wv[TOPK]; float ws = 0.f;
        #pragma unroll
        for (int s2 = 0; s2 < TOPK; s2++) {
            int bi = 0; float bv = -1.f;
            #pragma unroll
            for (int e = 0; e < NEXP; e++) if (p[e] > bv) { bv = p[e]; bi = e; }
            idx[s2] = bi; wv[s2] = bv; ws += bv; p[bi] = -2.f;
        }
        const float invw = 1.f/ws;
        #pragma unroll
        for (int s2 = 0; s2 < TOPK; s2++) {
            g_topk_idx[t*TOPK+s2] = idx[s2];
            g_topk_w[t*TOPK+s2]   = wv[s2]*invw;
        }
    }
}

// ---------------- setup: count + prefix + scatter, one block -----------------
__global__ void moe_setup() {
    __shared__ int sc[NEXP], sf[NEXP], so[NEXP];
    const int tid = threadIdx.x;      // 1024 threads, one per token
    if (tid < NEXP) { sc[tid] = 0; sf[tid] = 0; }
    __syncthreads();
    int es[TOPK];
    #pragma unroll
    for (int s = 0; s < TOPK; s++) {
        es[s] = g_topk_idx[tid*TOPK + s];
        atomicAdd(&sc[es[s]], 1);
    }
    __syncthreads();
    if (tid == 0) {
        int s = 0;
        #pragma unroll
        for (int e = 0; e < NEXP; e++) { so[e] = s; g_off[e] = s; s += sc[e]; }
        g_off[NEXP] = s;
    }
    __syncthreads();
    #pragma unroll
    for (int s = 0; s < TOPK; s++) {
        int e = es[s];
        int p = so[e] + atomicAdd(&sf[e], 1);
        g_assign_token[p]     = tid;
        g_token_pos[tid*TOPK+s] = p;
    }
}

// ---------------- gather + convert to fp16 ----------------------------------
__global__ void moe_gather(const float* __restrict__ x) {
    int id = blockIdx.x*blockDim.x + threadIdx.x;
    int p = id / (DMODEL/4);
    int q = id % (DMODEL/4);
    int t = g_assign_token[p];
    float4 v = ((const float4*)x)[(size_t)t*(DMODEL/4) + q];
    uint2 h;
    h.x = pack_h2(v.x, v.y);
    h.y = pack_h2(v.z, v.w);
    *(uint2*)(g_Xg_h + (size_t)p*DMODEL + q*4) = h;
}

// ===================== GEMM1 (fp16 mma, 3-stage, unrolled x3) ================
// BM=128, B tile = 128 smem rows (64 W1 + 64 V1 interleaved by 16), BK=32.
// SMEM row: 32 fp16 = 64B data + 16B pad = 80B. Stage: A 10240 | B 10240.
// 3 stages = 61440 dynamic; 2 CTAs/SM.
#define G1_STAGE 20480
#define G1_NCH   (DMODEL/32)   // 24 (divisible by 3)

__global__ __launch_bounds__(256, 2) void moe_gemm1_mma(const float* __restrict__ w1,
                                                        const float* __restrict__ v1) {
    const int e    = blockIdx.z;
    const int base = g_off[e];
    const int cnt  = g_off[e+1] - base;
    const int m0   = blockIdx.y * 128;
    if (m0 >= cnt) return;
    const int n0w  = blockIdx.x * 64;

    extern __shared__ char smem[];
    const uint32_t smb = smem_u32(smem);

    const int tid = threadIdx.x, lane = tid & 31, wid = tid >> 5;
    const int wm = wid >> 2, wn = wid & 3;     // 2 x 4 warp grid; warp tile 64x32

    // ---- A via cp.async (fp16) ----
    const int crow  = tid >> 1;                 // 0..127
    const int cpair = tid & 1;
    const uint32_t asz = ((m0 + crow) < cnt) ? 16u : 0u;
    const uint16_t* aH = g_Xg_h + (size_t)(base + m0 + crow)*DMODEL + cpair*16;
    const uint32_t adst = smb + (uint32_t)crow*80 + cpair*32;

    // ---- B: fp32 LDG + fp16 cvt + STS (rows 0-63 W1, 64-127 V1 by 16) ----
    const int brow  = tid >> 1;
    const int bhalf = tid & 1;
    const int grp   = brow >> 5, wi = brow & 31;
    const float* bsrc = (wi < 16)
        ? (w1 + (size_t)e*FFN*DMODEL + (size_t)(n0w + grp*16 + wi)*DMODEL)
        : (v1 + (size_t)e*FFN*DMODEL + (size_t)(n0w + grp*16 + (wi-16))*DMODEL);
    const float* bptr = bsrc + bhalf*16;
    const uint32_t boff = (uint32_t)brow*80 + bhalf*32;

    const int rl = (lane & 7) + ((lane >> 3) & 1) * 8;
    const int kl = (lane >> 4) * 16;

    float acc[4][4][4];
    #pragma unroll
    for (int i = 0; i < 4; i++)
        #pragma unroll
        for (int j = 0; j < 4; j++)
            #pragma unroll
            for (int r = 0; r < 4; r++) acc[i][j][r] = 0.f;

    float4 b4[4];

    #define G1_CPA(c, st) do { \
        if ((c) < G1_NCH) { \
            const uint32_t d = adst + (st)*G1_STAGE; \
            CPA16(d,      aH + (size_t)(c)*32,     asz); \
            CPA16(d + 16, aH + (size_t)(c)*32 + 8, asz); \
        } \
        CP_COMMIT(); \
    } while (0)

    #define G1_LDGB(c) do { \
        const float4* bp = (const float4*)(bptr + (size_t)(c)*32); \
        b4[0]=bp[0]; b4[1]=bp[1]; b4[2]=bp[2]; b4[3]=bp[3]; \
    } while (0)

    #define G1_STSB(st) do { \
        char* s_ = smem + (st)*G1_STAGE + 10240; \
        uint4 h; \
        h.x = pack_h2(b4[0].x, b4[0].y); h.y = pack_h2(b4[0].z, b4[0].w); \
        h.z = pack_h2(b4[1].x, b4[1].y); h.w = pack_h2(b4[1].z, b4[1].w); \
        *(uint4*)(s_ + boff) = h; \
        h.x = pack_h2(b4[2].x, b4[2].y); h.y = pack_h2(b4[2].z, b4[2].w); \
        h.z = pack_h2(b4[3].x, b4[3].y); h.w = pack_h2(b4[3].z, b4[3].w); \
        *(uint4*)(s_ + boff + 16) = h; \
    } while (0)

    // one chunk: compute stage SA; chunk c+1 STS-> stage SB; prefetch c+2 -> SC
    #define G1_CHUNK(c, SA, SB, SC) do { \
        const uint32_t sA = smb + (SA)*G1_STAGE; \
        const uint32_t sB = sA + 10240; \
        G1_CPA((c) + 2, SC); \
        if ((c) + 2 < G1_NCH) G1_LDGB((c) + 2); /* issued later below via schedule */ \
        uint32_t bh[2][4]; \
        uint32_t ah[2][4]; \
        _Pragma("unroll") \
        for (int s16 = 0; s16 < 2; s16++) { \
            const int kb = s16*32 + kl; \
            _Pragma("unroll") \
            for (int jt = 0; jt < 2; jt++) { \
                const uint32_t ba = (uint32_t)(wn*32 + jt*16 + rl)*80 + kb; \
                LDSM_X4(bh[jt], sB + ba); \
            } \
            LDSM_X4(ah[0], sA + (uint32_t)(wm*64 + rl)*80 + kb); \
            _Pragma("unroll") \
            for (int i = 0; i < 4; i++) { \
                const int p = i & 1; \
                if (i < 3) \
                    LDSM_X4(ah[p ^ 1], sA + (uint32_t)(wm*64 + (i+1)*16 + rl)*80 + kb); \
                _Pragma("unroll") \
                for (int jn = 0; jn < 4; jn++) { \
                    const int jt = jn >> 1, hf = jn & 1; \
                    MMA_F16(acc[i][jn], ah[p], bh[jt][hf], bh[jt][hf+2]); \
                } \
                if (s16 == 0 && i == 1 && ((c) + 1 < G1_NCH)) G1_STSB(SB); \
            } \
        } \
        if ((c) + 1 < G1_NCH) { \
            CP_WAIT1(); \
            __syncthreads(); \
        } \
    } while (0)

    // ---- prologue ----
    G1_CPA(0, 0);
    G1_CPA(1, 1);
    G1_LDGB(0);  G1_STSB(0);
    G1_LDGB(1);
    CP_WAIT1();
    __syncthreads();

    // NOTE on G1_CHUNK's LDGB placement: the STSB(SB) inside the chunk for c+1
    // consumes b4 loaded for chunk c+1 BEFORE this chunk's LDGB(c+2) overwrite.
    // To preserve that ordering we load c+2 AFTER the STSB. The macro above
    // issues LDGB early only as a comment; the real schedule is below.
    #undef G1_CHUNK
    #define G1_CHUNK(c, SA, SB, SC) do { \
        const uint32_t sA = smb + (SA)*G1_STAGE; \
        const uint32_t sB = sA + 10240; \
        G1_CPA((c) + 2, SC); \
        uint32_t bh[2][4]; \
        uint32_t ah[2][4]; \
        _Pragma("unroll") \
        for (int s16 = 0; s16 < 2; s16++) { \
            const int kb = s16*32 + kl; \
            _Pragma("unroll") \
            for (int jt = 0; jt < 2; jt++) { \
                const uint32_t ba = (uint32_t)(wn*32 + jt*16 + rl)*80 + kb; \
                LDSM_X4(bh[jt], sB + ba); \
            } \
            LDSM_X4(ah[0], sA + (uint32_t)(wm*64 + rl)*80 + kb); \
            _Pragma("unroll") \
            for (int i = 0; i < 4; i++) { \
                const int p = i & 1; \
                if (i < 3) \
                    LDSM_X4(ah[p ^ 1], sA + (uint32_t)(wm*64 + (i+1)*16 + rl)*80 + kb); \
                _Pragma("unroll") \
                for (int jn = 0; jn < 4; jn++) { \
                    const int jt = jn >> 1, hf = jn & 1; \
                    MMA_F16(acc[i][jn], ah[p], bh[jt][hf], bh[jt][hf+2]); \
                } \
                if (s16 == 0) { \
                    if (i == 1 && ((c) + 1 < G1_NCH)) G1_STSB(SB); \
                    if (i == 2 && ((c) + 2 < G1_NCH)) G1_LDGB((c) + 2); \
                } \
            } \
        } \
        if ((c) + 1 < G1_NCH) { \
            CP_WAIT1(); \
            __syncthreads(); \
        } \
    } while (0)

    #pragma unroll 1
    for (int c0 = 0; c0 < G1_NCH; c0 += 3) {
        G1_CHUNK(c0    , 0, 1, 2);
        G1_CHUNK(c0 + 1, 1, 2, 0);
        G1_CHUNK(c0 + 2, 2, 0, 1);
    }

    // ---- epilogue: silu(gate)*up -> fp16 ----
    const int r0 = lane >> 2;
    const int cq = (lane & 3) * 2;
    #pragma unroll
    for (int i = 0; i < 4; i++) {
        const int mb = m0 + wm*64 + i*16;
        #pragma unroll
        for (int rg = 0; rg < 2; rg++) {
            const int m = mb + rg*8 + r0;
            if (m < cnt) {
                const size_t rowb = (size_t)(base + m)*FFN;
                #pragma unroll
                for (int jj = 0; jj < 2; jj++) {
                    const int cc = n0w + wn*16 + jj*8 + cq;
                    float g0 = acc[i][jj][rg*2+0], g1 = acc[i][jj][rg*2+1];
                    float u0 = acc[i][jj+2][rg*2+0], u1 = acc[i][jj+2][rg*2+1];
                    float o0 = g0/(1.f+__expf(-g0))*u0;
                    float o1 = g1/(1.f+__expf(-g1))*u1;
                    *(uint32_t*)(g_act_h + rowb + cc) = pack_h2(o0, o1);
                }
            }
        }
    }
    #undef G1_CPA
    #undef G1_LDGB
    #undef G1_STSB
    #undef G1_CHUNK
}

// ===================== GEMM2 (fp16 mma, BN=128, unrolled x3) =================
// BM=128, BN=128 (128 W2 rows), BK=32. Same geometry as GEMM1.
// Stage: A 10240 | B 10240 = 20480; 3 stages = 61440; 2 CTAs/SM.
#define G2_STAGE 20480
#define G2_NCH   (FFN/32)   // 96 (divisible by 3)

__global__ __launch_bounds__(256, 2) void moe_gemm2_mma(const float* __restrict__ w2) {
    const int e    = blockIdx.z;
    const int base = g_off[e];
    const int cnt  = g_off[e+1] - base;
    const int m0   = blockIdx.y * 128;
    if (m0 >= cnt) return;
    const int n0   = blockIdx.x * 128;

    extern __shared__ char smem[];
    const uint32_t smb = smem_u32(smem);

    const int tid = threadIdx.x, lane = tid & 31, wid = tid >> 5;
    const int wm = wid >> 2, wn = wid & 3;     // 2 x 4 warp grid; warp tile 64x32

    // ---- A via cp.async (fp16 act) ----
    const int crow  = tid >> 1;
    const int cpair = tid & 1;
    const uint32_t asz = ((m0 + crow) < cnt) ? 16u : 0u;
    const uint16_t* aH = g_act_h + (size_t)(base + m0 + crow)*FFN + cpair*16;
    const uint32_t adst = smb + (uint32_t)crow*80 + cpair*32;

    // ---- B: 128 W2 rows, 2 threads per row ----
    const int brow  = tid >> 1;                 // 0..127
    const int bhalf = tid & 1;
    const float* bptr = w2 + (size_t)e*DMODEL*FFN + (size_t)(n0 + brow)*FFN + bhalf*16;
    const uint32_t boff = (uint32_t)brow*80 + bhalf*32;

    const int rl = (lane & 7) + ((lane >> 3) & 1) * 8;
    const int kl = (lane >> 4) * 16;

    float acc[4][4][4];
    #pragma unroll
    for (int i = 0; i < 4; i++)
        #pragma unroll
        for (int j = 0; j < 4; j++)
            #pragma unroll
            for (int r = 0; r < 4; r++) acc[i][j][r] = 0.f;

    float4 b4[4];

    #define G2_CPA(c, st) do { \
        if ((c) < G2_NCH) { \
            const uint32_t d = adst + (st)*G2_STAGE; \
            CPA16(d,      aH + (size_t)(c)*32,     asz); \
            CPA16(d + 16, aH + (size_t)(c)*32 + 8, asz); \
        } \
        CP_COMMIT(); \
    } while (0)

    #define G2_LDGB(c) do { \
        const float4* bp = (const float4*)(bptr + (size_t)(c)*32); \
        b4[0]=bp[0]; b4[1]=bp[1]; b4[2]=bp[2]; b4[3]=bp[3]; \
    } while (0)

    #define G2_STSB(st) do { \
        char* s_ = smem + (st)*G2_STAGE + 10240; \
        uint4 h; \
        h.x = pack_h2(b4[0].x, b4[0].y); h.y = pack_h2(b4[0].z, b4[0].w); \
        h.z = pack_h2(b4[1].x, b4[1].y); h.w = pack_h2(b4[1].z, b4[1].w); \
        *(uint4*)(s_ + boff) = h; \
        h.x = pack_h2(b4[2].x, b4[2].y); h.y = pack_h2(b4[2].z, b4[2].w); \
        h.z = pack_h2(b4[3].x, b4[3].y); h.w = pack_h2(b4[3].z, b4[3].w); \
        *(uint4*)(s_ + boff + 16) = h; \
    } while (0)

    #define G2_CHUNK(c, SA, SB, SC) do { \
        const uint32_t sA = smb + (SA)*G2_STAGE; \
        const uint32_t sB = sA + 10240; \
        G2_CPA((c) + 2, SC); \
        uint32_t bh[2][4]; \
        uint32_t ah[2][4]; \
        _Pragma("unroll") \
        for (int s16 = 0; s16 < 2; s16++) { \
            const int kb = s16*32 + kl; \
            _Pragma("unroll") \
            for (int jt = 0; jt < 2; jt++) { \
                const uint32_t ba = (uint32_t)(wn*32 + jt*16 + rl)*80 + kb; \
                LDSM_X4(bh[jt], sB + ba); \
            } \
            LDSM_X4(ah[0], sA + (uint32_t)(wm*64 + rl)*80 + kb); \
            _Pragma("unroll") \
            for (int i = 0; i < 4; i++) { \
                const int p = i & 1; \
                if (i < 3) \
                    LDSM_X4(ah[p ^ 1], sA + (uint32_t)(wm*64 + (i+1)*16 + rl)*80 + kb); \
                _Pragma("unroll") \
                for (int jn = 0; jn < 4; jn++) { \
                    const int jt = jn >> 1, hf = jn & 1; \
                    MMA_F16(acc[i][jn], ah[p], bh[jt][hf], bh[jt][hf+2]); \
                } \
                if (s16 == 0) { \
                    if (i == 1 && ((c) + 1 < G2_NCH)) G2_STSB(SB); \
                    if (i == 2 && ((c) + 2 < G2_NCH)) G2_LDGB((c) + 2); \
                } \
            } \
        } \
        if ((c) + 1 < G2_NCH) { \
            CP_WAIT1(); \
            __syncthreads(); \
        } \
    } while (0)

    // ---- prologue ----
    G2_CPA(0, 0);
    G2_CPA(1, 1);
    G2_LDGB(0);  G2_STSB(0);
    G2_LDGB(1);
    CP_WAIT1();
    __syncthreads();

    #pragma unroll 1
    for (int c0 = 0; c0 < G2_NCH; c0 += 3) {
        G2_CHUNK(c0    , 0, 1, 2);
        G2_CHUNK(c0 + 1, 1, 2, 0);
        G2_CHUNK(c0 + 2, 2, 0, 1);
    }

    // ---- epilogue: fp16 rows of g_down_h ----
    const int r0 = lane >> 2;
    const int cq = (lane & 3) * 2;
    #pragma unroll
    for (int i = 0; i < 4; i++) {
        const int mb = m0 + wm*64 + i*16;
        #pragma unroll
        for (int rg = 0; rg < 2; rg++) {
            const int m = mb + rg*8 + r0;
            if (m < cnt) {
                uint16_t* orow = g_down_h + (size_t)(base + m)*DMODEL;
                #pragma unroll
                for (int jn = 0; jn < 4; jn++) {
                    const int cc = n0 + wn*32 + jn*8 + cq;
                    *(uint32_t*)(orow + cc) = pack_h2(acc[i][jn][rg*2+0], acc[i][jn][rg*2+1]);
                }
            }
        }
    }
    #undef G2_CPA
    #undef G2_LDGB
    #undef G2_STSB
    #undef G2_CHUNK
}

// ---------------- combine: out[t] = sum_slot w * down[pos(t,slot)] ----------
__global__ void moe_combine(float* __restrict__ out) {
    int id = blockIdx.x*blockDim.x + threadIdx.x;
    int t = id / (DMODEL/4);
    int q = id % (DMODEL/4);
    float4 acc = make_float4(0,0,0,0);
    #pragma unroll
    for (int s = 0; s < TOPK; s++) {
        int   p = g_token_pos[t*TOPK+s];
        float w = g_topk_w[t*TOPK+s];
        uint2 hv = *(const uint2*)(g_down_h + (size_t)p*DMODEL + q*4);
        float2 v0 = unpack_h2(hv.x);
        float2 v1 = unpack_h2(hv.y);
        acc.x = fmaf(w, v0.x, acc.x);
        acc.y = fmaf(w, v0.y, acc.y);
        acc.z = fmaf(w, v1.x, acc.z);
        acc.w = fmaf(w, v1.y, acc.w);
    }
    ((float4*)out)[id] = acc;
}

// ---------------- launch ----------------------------------------------------
extern "C" void kernel_launch(void* const* d_in, const int* in_sizes, int n_in,
                              void* d_out, int out_size) {
    const float* x  = (const float*)d_in[0];
    const float* rw = (const float*)d_in[1];
    const float* w1 = (const float*)d_in[2];
    const float* v1 = (const float*)d_in[3];
    const float* w2 = (const float*)d_in[4];
    float* out = (float*)d_out;

    cudaFuncSetAttribute(moe_gemm1_mma, cudaFuncAttributeMaxDynamicSharedMemorySize, 3*G1_STAGE);
    cudaFuncSetAttribute(moe_gemm2_mma, cudaFuncAttributeMaxDynamicSharedMemorySize, 3*G2_STAGE);

    moe_router<<<T_TOK, 128>>>(x, rw);                // launch 1
    moe_setup<<<1, 1024>>>();                         // launch 2
    moe_gather<<<(NASSIGN*(DMODEL/4))/256, 256>>>(x); // launch 3

    dim3 g1(FFN/64, NASSIGN/128, NEXP);               // launch 4 <- profiled slot
    moe_gemm1_mma<<<g1, 256, 3*G1_STAGE>>>(w1, v1);

    dim3 g2(DMODEL/128, NASSIGN/128, NEXP);           // 6 x 32 x 16
    moe_gemm2_mma<<<g2, 256, 3*G2_STAGE>>>(w2);

    moe_combine<<<(T_TOK*(DMODEL/4))/256, 256>>>(out);
}

// round 15
// speedup vs baseline: 1.0137x; 1.0081x over previous
#include <cuda_runtime.h>
#include <cuda_fp16.h>
#include <math.h>
#include <stdint.h>

#define T_TOK   1024
#define DMODEL  768
#define NEXP    16
#define FFN     3072
#define TOPK    4
#define NASSIGN (T_TOK*TOPK)

// ---------------- scratch (device globals; no allocations allowed) ----------
__device__ uint16_t g_Xg_h[(size_t)NASSIGN*DMODEL];   // gathered activations, fp16
__device__ uint16_t g_act_h[(size_t)NASSIGN*FFN];     // silu(gate)*up, fp16
__device__ uint16_t g_down_h[(size_t)NASSIGN*DMODEL]; // down-proj rows (fp16)
__device__ int      g_topk_idx[T_TOK*TOPK];
__device__ float    g_topk_w[T_TOK*TOPK];
__device__ int      g_off[NEXP+1];
__device__ int      g_assign_token[NASSIGN];
__device__ int      g_token_pos[T_TOK*TOPK];

// ================= helpers =================
__device__ __forceinline__ uint32_t smem_u32(const void* p) {
    uint32_t a;
    asm("{ .reg .u64 t; cvta.to.shared.u64 t, %1; cvt.u32.u64 %0, t; }" : "=r"(a) : "l"(p));
    return a;
}
__device__ __forceinline__ uint32_t pack_h2(float x, float y) {
    uint32_t h;
    asm("cvt.rn.f16x2.f32 %0, %1, %2;" : "=r"(h) : "f"(y), "f"(x));
    return h;
}
__device__ __forceinline__ float2 unpack_h2(uint32_t h) {
    float lo, hi;
    asm("{ .reg .b16 a, b;\n\t mov.b32 {a, b}, %2;\n\t cvt.f32.f16 %0, a;\n\t cvt.f32.f16 %1, b; }"
        : "=f"(lo), "=f"(hi) : "r"(h));
    return make_float2(lo, hi);
}

#define LDSM_X4(r, addr) \
    asm volatile("ldmatrix.sync.aligned.m8n8.x4.shared.b16 {%0,%1,%2,%3}, [%4];" \
        : "=r"((r)[0]),"=r"((r)[1]),"=r"((r)[2]),"=r"((r)[3]) : "r"(addr))

#define MMA_F16(d, a, b0, b1) \
    asm volatile("mma.sync.aligned.m16n8k16.row.col.f32.f16.f16.f32 " \
        "{%0,%1,%2,%3},{%4,%5,%6,%7},{%8,%9},{%0,%1,%2,%3};" \
        : "+f"((d)[0]),"+f"((d)[1]),"+f"((d)[2]),"+f"((d)[3]) \
        : "r"((a)[0]),"r"((a)[1]),"r"((a)[2]),"r"((a)[3]),"r"(b0),"r"(b1))

#define CPA16(dst, src, sz) \
    asm volatile("cp.async.cg.shared.global [%0], [%1], 16, %2;" :: "r"(dst), "l"(src), "r"(sz) : "memory")
#define CP_COMMIT() asm volatile("cp.async.commit_group;" ::: "memory")
#define CP_WAIT1()  asm volatile("cp.async.wait_group 1;" ::: "memory")

// ---------------- router: logits -> softmax -> top4 -> renorm ---------------
__global__ void moe_router(const float* __restrict__ x, const float* __restrict__ rw) {
    const int t = blockIdx.x;
    __shared__ float sx[DMODEL];
    __shared__ float slog[NEXP];
    const int tid = threadIdx.x;
    const float4* xr = (const float4*)(x + (size_t)t*DMODEL);
    float4* sx4 = (float4*)sx;
    for (int i = tid; i < DMODEL/4; i += 128) sx4[i] = xr[i];
    __syncthreads();

    const int warp = tid >> 5, lane = tid & 31;
    for (int e = warp; e < NEXP; e += 4) {
        const float* w = rw + (size_t)e*DMODEL;
        float s = 0.f;
        for (int k = lane; k < DMODEL; k += 32) s = fmaf(sx[k], w[k], s);
        #pragma unroll
        for (int o = 16; o > 0; o >>= 1) s += __shfl_down_sync(0xffffffffu, s, o);
        if (lane == 0) slog[e] = s;
    }
    __syncthreads();

    if (tid == 0) {
        float m = -1e30f;
        #pragma unroll
        for (int e = 0; e < NEXP; e++) m = fmaxf(m, slog[e]);
        float p[NEXP]; float sum = 0.f;
        #pragma unroll
        for (int e = 0; e < NEXP; e++) { p[e] = __expf(slog[e]-m); sum += p[e]; }
        const float inv = 1.f/sum;
        #pragma unroll
        for (int e = 0; e < NEXP; e++) p[e] *= inv;

        int idx[TOPK]; float wv[TOPK]; float ws = 0.f;
        #pragma unroll
        for (int s2 = 0; s2 < TOPK; s2++) {
            int bi = 0; float bv = -1.f;
            #pragma unroll
            for (int e = 0; e < NEXP; e++) if (p[e] > bv) { bv = p[e]; bi = e; }
            idx[s2] = bi; wv[s2] = bv; ws += bv; p[bi] = -2.f;
        }
        const float invw = 1.f/ws;
        #pragma unroll
        for (int s2 = 0; s2 < TOPK; s2++) {
            g_topk_idx[t*TOPK+s2] = idx[s2];
            g_topk_w[t*TOPK+s2]   = wv[s2]*invw;
        }
    }
}

// ---------------- setup: count + prefix + scatter, one block -----------------
__global__ void moe_setup() {
    __shared__ int sc[NEXP], sf[NEXP], so[NEXP];
    const int tid = threadIdx.x;      // 1024 threads, one per token
    if (tid < NEXP) { sc[tid] = 0; sf[tid] = 0; }
    __syncthreads();
    int es[TOPK];
    #pragma unroll
    for (int s = 0; s < TOPK; s++) {
        es[s] = g_topk_idx[tid*TOPK + s];
        atomicAdd(&sc[es[s]], 1);
    }
    __syncthreads();
    if (tid == 0) {
        int s = 0;
        #pragma unroll
        for (int e = 0; e < NEXP; e++) { so[e] = s; g_off[e] = s; s += sc[e]; }
        g_off[NEXP] = s;
    }
    __syncthreads();
    #pragma unroll
    for (int s = 0; s < TOPK; s++) {
        int e = es[s];
        int p = so[e] + atomicAdd(&sf[e], 1);
        g_assign_token[p]     = tid;
        g_token_pos[tid*TOPK+s] = p;
    }
}

// ---------------- gather + convert to fp16 ----------------------------------
__global__ void moe_gather(const float* __restrict__ x) {
    int id = blockIdx.x*blockDim.x + threadIdx.x;
    int p = id / (DMODEL/4);
    int q = id % (DMODEL/4);
    int t = g_assign_token[p];
    float4 v = ((const float4*)x)[(size_t)t*(DMODEL/4) + q];
    uint2 h;
    h.x = pack_h2(v.x, v.y);
    h.y = pack_h2(v.z, v.w);
    *(uint2*)(g_Xg_h + (size_t)p*DMODEL + q*4) = h;
}

// ===================== GEMM1 (fp16 mma, 3-stage + frag pipeline) =============
// BM=128, B tile = 128 smem rows (64 W1 + 64 V1 interleaved by 16), BK=32.
// SMEM row: 32 fp16 = 64B data + 16B pad = 80B. Stage: A 10240 | B 10240.
// 3 stages = 61440 dynamic; 2 CTAs/SM.
#define G1_STAGE 20480
#define G1_NCH   (DMODEL/32)   // 24

__global__ __launch_bounds__(256, 2) void moe_gemm1_mma(const float* __restrict__ w1,
                                                        const float* __restrict__ v1) {
    const int e    = blockIdx.z;
    const int base = g_off[e];
    const int cnt  = g_off[e+1] - base;
    const int m0   = blockIdx.y * 128;
    if (m0 >= cnt) return;
    const int n0w  = blockIdx.x * 64;

    extern __shared__ char smem[];
    const uint32_t smb = smem_u32(smem);

    const int tid = threadIdx.x, lane = tid & 31, wid = tid >> 5;
    const int wm = wid >> 2, wn = wid & 3;     // 2 x 4 warp grid; warp tile 64x32

    // ---- A via cp.async (fp16) ----
    const int crow  = tid >> 1;                 // 0..127
    const int cpair = tid & 1;
    const uint32_t asz = ((m0 + crow) < cnt) ? 16u : 0u;
    const uint16_t* aH = g_Xg_h + (size_t)(base + m0 + crow)*DMODEL + cpair*16;
    const uint32_t adst = smb + (uint32_t)crow*80 + cpair*32;

    // ---- B: fp32 LDG + fp16 cvt + STS (rows 0-63 W1, 64-127 V1 by 16) ----
    const int brow  = tid >> 1;
    const int bhalf = tid & 1;
    const int grp   = brow >> 5, wi = brow & 31;
    const float* bsrc = (wi < 16)
        ? (w1 + (size_t)e*FFN*DMODEL + (size_t)(n0w + grp*16 + wi)*DMODEL)
        : (v1 + (size_t)e*FFN*DMODEL + (size_t)(n0w + grp*16 + (wi-16))*DMODEL);
    const float* bptr = bsrc + bhalf*16;
    const uint32_t boff = (uint32_t)brow*80 + bhalf*32;

    const int rl = (lane & 7) + ((lane >> 3) & 1) * 8;
    const int kl = (lane >> 4) * 16;

    float acc[4][4][4];
    #pragma unroll
    for (int i = 0; i < 4; i++)
        #pragma unroll
        for (int j = 0; j < 4; j++)
            #pragma unroll
            for (int r = 0; r < 4; r++) acc[i][j][r] = 0.f;

    float4 b4[4];

    #define G1_CPA(c) do { \
        if ((c) < G1_NCH) { \
            const uint32_t d = adst + ((c)%3)*G1_STAGE; \
            CPA16(d,      aH + (size_t)(c)*32,     asz); \
            CPA16(d + 16, aH + (size_t)(c)*32 + 8, asz); \
        } \
        CP_COMMIT(); \
    } while (0)

    #define G1_LDGB(c) do { \
        const float4* bp = (const float4*)(bptr + (size_t)(c)*32); \
        b4[0]=bp[0]; b4[1]=bp[1]; b4[2]=bp[2]; b4[3]=bp[3]; \
    } while (0)

    #define G1_STSB(c) do { \
        char* s_ = smem + ((c)%3)*G1_STAGE + 10240; \
        uint4 h; \
        h.x = pack_h2(b4[0].x, b4[0].y); h.y = pack_h2(b4[0].z, b4[0].w); \
        h.z = pack_h2(b4[1].x, b4[1].y); h.w = pack_h2(b4[1].z, b4[1].w); \
        *(uint4*)(s_ + boff) = h; \
        h.x = pack_h2(b4[2].x, b4[2].y); h.y = pack_h2(b4[2].z, b4[2].w); \
        h.z = pack_h2(b4[3].x, b4[3].y); h.w = pack_h2(b4[3].z, b4[3].w); \
        *(uint4*)(s_ + boff + 16) = h; \
    } while (0)

    // ---- prologue ----
    G1_CPA(0);                 // group -> chunk 0
    G1_CPA(1);                 // group -> chunk 1
    G1_LDGB(0);  G1_STSB(0);   // B0 -> stage 0
    G1_LDGB(1);                // b4 = B1
    CP_WAIT1();                // A0 landed (A1 may be in flight)
    __syncthreads();

    for (int c = 0; c < G1_NCH; c++) {
        const uint32_t sA = smb + (c%3)*G1_STAGE;
        const uint32_t sB = sA + 10240;
        G1_CPA(c + 2);         // prefetch A two chunks ahead

        uint32_t bh[2][4];
        uint32_t ah[2][4];

        #pragma unroll
        for (int s16 = 0; s16 < 2; s16++) {
            const int kb = s16*32 + kl;
            // B frags for this s16
            #pragma unroll
            for (int jt = 0; jt < 2; jt++) {
                const uint32_t ba = (uint32_t)(wn*32 + jt*16 + rl)*80 + kb;
                LDSM_X4(bh[jt], sB + ba);
            }
            // A frag pipeline across i
            LDSM_X4(ah[0], sA + (uint32_t)(wm*64 + rl)*80 + kb);
            #pragma unroll
            for (int i = 0; i < 4; i++) {
                const int p = i & 1;
                if (i < 3)
                    LDSM_X4(ah[p ^ 1], sA + (uint32_t)(wm*64 + (i+1)*16 + rl)*80 + kb);
                #pragma unroll
                for (int jn = 0; jn < 4; jn++) {
                    const int jt = jn >> 1, hf = jn & 1;
                    MMA_F16(acc[i][jn], ah[p], bh[jt][hf], bh[jt][hf+2]);
                }
                if (s16 == 0) {
                    if (i == 1 && (c + 1 < G1_NCH)) G1_STSB(c + 1);
                    if (i == 2 && (c + 2 < G1_NCH)) G1_LDGB(c + 2);
                }
            }
        }

        if (c + 1 < G1_NCH) {
            CP_WAIT1();        // A(c+1) landed; A(c+2) may be in flight
            __syncthreads();
        }
    }

    // ---- epilogue: silu(gate)*up -> fp16 ----
    const int r0 = lane >> 2;
    const int cq = (lane & 3) * 2;
    #pragma unroll
    for (int i = 0; i < 4; i++) {
        const int mb = m0 + wm*64 + i*16;
        #pragma unroll
        for (int rg = 0; rg < 2; rg++) {
            const int m = mb + rg*8 + r0;
            if (m < cnt) {
                const size_t rowb = (size_t)(base + m)*FFN;
                #pragma unroll
                for (int jj = 0; jj < 2; jj++) {
                    const int cc = n0w + wn*16 + jj*8 + cq;
                    float g0 = acc[i][jj][rg*2+0], g1 = acc[i][jj][rg*2+1];
                    float u0 = acc[i][jj+2][rg*2+0], u1 = acc[i][jj+2][rg*2+1];
                    float o0 = g0/(1.f+__expf(-g0))*u0;
                    float o1 = g1/(1.f+__expf(-g1))*u1;
                    *(uint32_t*)(g_act_h + rowb + cc) = pack_h2(o0, o1);
                }
            }
        }
    }
    #undef G1_CPA
    #undef G1_LDGB
    #undef G1_STSB
}

// ===================== GEMM2 (fp16 mma, BN=128, 3-stage + frag pipeline) =====
// BM=128, BN=128 (128 W2 rows), BK=32. Same geometry as GEMM1.
// Stage: A 10240 | B 10240 = 20480; 3 stages = 61440; 2 CTAs/SM.
#define G2_STAGE 20480
#define G2_NCH   (FFN/32)   // 96

__global__ __launch_bounds__(256, 2) void moe_gemm2_mma(const float* __restrict__ w2) {
    const int e    = blockIdx.z;
    const int base = g_off[e];
    const int cnt  = g_off[e+1] - base;
    const int m0   = blockIdx.y * 128;
    if (m0 >= cnt) return;
    const int n0   = blockIdx.x * 128;

    extern __shared__ char smem[];
    const uint32_t smb = smem_u32(smem);

    const int tid = threadIdx.x, lane = tid & 31, wid = tid >> 5;
    const int wm = wid >> 2, wn = wid & 3;     // 2 x 4 warp grid; warp tile 64x32

    // ---- A via cp.async (fp16 act) ----
    const int crow  = tid >> 1;
    const int cpair = tid & 1;
    const uint32_t asz = ((m0 + crow) < cnt) ? 16u : 0u;
    const uint16_t* aH = g_act_h + (size_t)(base + m0 + crow)*FFN + cpair*16;
    const uint32_t adst = smb + (uint32_t)crow*80 + cpair*32;

    // ---- B: 128 W2 rows, 2 threads per row ----
    const int brow  = tid >> 1;                 // 0..127
    const int bhalf = tid & 1;
    const float* bptr = w2 + (size_t)e*DMODEL*FFN + (size_t)(n0 + brow)*FFN + bhalf*16;
    const uint32_t boff = (uint32_t)brow*80 + bhalf*32;

    const int rl = (lane & 7) + ((lane >> 3) & 1) * 8;
    const int kl = (lane >> 4) * 16;

    float acc[4][4][4];
    #pragma unroll
    for (int i = 0; i < 4; i++)
        #pragma unroll
        for (int j = 0; j < 4; j++)
            #pragma unroll
            for (int r = 0; r < 4; r++) acc[i][j][r] = 0.f;

    float4 b4[4];

    #define G2_CPA(c) do { \
        if ((c) < G2_NCH) { \
            const uint32_t d = adst + ((c)%3)*G2_STAGE; \
            CPA16(d,      aH + (size_t)(c)*32,     asz); \
            CPA16(d + 16, aH + (size_t)(c)*32 + 8, asz); \
        } \
        CP_COMMIT(); \
    } while (0)

    #define G2_LDGB(c) do { \
        const float4* bp = (const float4*)(bptr + (size_t)(c)*32); \
        b4[0]=bp[0]; b4[1]=bp[1]; b4[2]=bp[2]; b4[3]=bp[3]; \
    } while (0)

    #define G2_STSB(c) do { \
        char* s_ = smem + ((c)%3)*G2_STAGE + 10240; \
        uint4 h; \
        h.x = pack_h2(b4[0].x, b4[0].y); h.y = pack_h2(b4[0].z, b4[0].w); \
        h.z = pack_h2(b4[1].x, b4[1].y); h.w = pack_h2(b4[1].z, b4[1].w); \
        *(uint4*)(s_ + boff) = h; \
        h.x = pack_h2(b4[2].x, b4[2].y); h.y = pack_h2(b4[2].z, b4[2].w); \
        h.z = pack_h2(b4[3].x, b4[3].y); h.w = pack_h2(b4[3].z, b4[3].w); \
        *(uint4*)(s_ + boff + 16) = h; \
    } while (0)

    // ---- prologue ----
    G2_CPA(0);
    G2_CPA(1);
    G2_LDGB(0);  G2_STSB(0);
    G2_LDGB(1);
    CP_WAIT1();
    __syncthreads();

    for (int c = 0; c < G2_NCH; c++) {
        const uint32_t sA = smb + (c%3)*G2_STAGE;
        const uint32_t sB = sA + 10240;
        G2_CPA(c + 2);

        uint32_t bh[2][4];
        uint32_t ah[2][4];

        #pragma unroll
        for (int s16 = 0; s16 < 2; s16++) {
            const int kb = s16*32 + kl;
            #pragma unroll
            for (int jt = 0; jt < 2; jt++) {
                const uint32_t ba = (uint32_t)(wn*32 + jt*16 + rl)*80 + kb;
                LDSM_X4(bh[jt], sB + ba);
            }
            LDSM_X4(ah[0], sA + (uint32_t)(wm*64 + rl)*80 + kb);
            #pragma unroll
            for (int i = 0; i < 4; i++) {
                const int p = i & 1;
                if (i < 3)
                    LDSM_X4(ah[p ^ 1], sA + (uint32_t)(wm*64 + (i+1)*16 + rl)*80 + kb);
                #pragma unroll
                for (int jn = 0; jn < 4; jn++) {
                    const int jt = jn >> 1, hf = jn & 1;
                    MMA_F16(acc[i][jn], ah[p], bh[jt][hf], bh[jt][hf+2]);
                }
                if (s16 == 0) {
                    if (i == 1 && (c + 1 < G2_NCH)) G2_STSB(c + 1);
                    if (i == 2 && (c + 2 < G2_NCH)) G2_LDGB(c + 2);
                }
            }
        }

        if (c + 1 < G2_NCH) {
            CP_WAIT1();
            __syncthreads();
        }
    }

    // ---- epilogue: fp16 rows of g_down_h ----
    const int r0 = lane >> 2;
    const int cq = (lane & 3) * 2;
    #pragma unroll
    for (int i = 0; i < 4; i++) {
        const int mb = m0 + wm*64 + i*16;
        #pragma unroll
        for (int rg = 0; rg < 2; rg++) {
            const int m = mb + rg*8 + r0;
            if (m < cnt) {
                uint16_t* orow = g_down_h + (size_t)(base + m)*DMODEL;
                #pragma unroll
                for (int jn = 0; jn < 4; jn++) {
                    const int cc = n0 + wn*32 + jn*8 + cq;
                    *(uint32_t*)(orow + cc) = pack_h2(acc[i][jn][rg*2+0], acc[i][jn][rg*2+1]);
                }
            }
        }
    }
    #undef G2_CPA
    #undef G2_LDGB
    #undef G2_STSB
}

// ---------------- combine: out[t] = sum_slot w * down[pos(t,slot)] ----------
__global__ void moe_combine(float* __restrict__ out) {
    int id = blockIdx.x*blockDim.x + threadIdx.x;
    int t = id / (DMODEL/4);
    int q = id % (DMODEL/4);
    float4 acc = make_float4(0,0,0,0);
    #pragma unroll
    for (int s = 0; s < TOPK; s++) {
        int   p = g_token_pos[t*TOPK+s];
        float w = g_topk_w[t*TOPK+s];
        uint2 hv = *(const uint2*)(g_down_h + (size_t)p*DMODEL + q*4);
        float2 v0 = unpack_h2(hv.x);
        float2 v1 = unpack_h2(hv.y);
        acc.x = fmaf(w, v0.x, acc.x);
        acc.y = fmaf(w, v0.y, acc.y);
        acc.z = fmaf(w, v1.x, acc.z);
        acc.w = fmaf(w, v1.y, acc.w);
    }
    ((float4*)out)[id] = acc;
}

// ---------------- launch ----------------------------------------------------
extern "C" void kernel_launch(void* const* d_in, const int* in_sizes, int n_in,
                              void* d_out, int out_size) {
    const float* x  = (const float*)d_in[0];
    const float* rw = (const float*)d_in[1];
    const float* w1 = (const float*)d_in[2];
    const float* v1 = (const float*)d_in[3];
    const float* w2 = (const float*)d_in[4];
    float* out = (float*)d_out;

    cudaFuncSetAttribute(moe_gemm1_mma, cudaFuncAttributeMaxDynamicSharedMemorySize, 3*G1_STAGE);
    cudaFuncSetAttribute(moe_gemm2_mma, cudaFuncAttributeMaxDynamicSharedMemorySize, 3*G2_STAGE);

    moe_router<<<T_TOK, 128>>>(x, rw);                // launch 1
    moe_setup<<<1, 1024>>>();                         // launch 2
    moe_gather<<<(NASSIGN*(DMODEL/4))/256, 256>>>(x); // launch 3

    dim3 g1(FFN/64, NASSIGN/128, NEXP);               // launch 4 <- profiled slot
    moe_gemm1_mma<<<g1, 256, 3*G1_STAGE>>>(w1, v1);

    dim3 g2(DMODEL/128, NASSIGN/128, NEXP);           // 6 x 32 x 16
    moe_gemm2_mma<<<g2, 256, 3*G2_STAGE>>>(w2);

    moe_combine<<<(T_TOK*(DMODEL/4))/256, 256>>>(out);
}

// round 16
// speedup vs baseline: 1.0154x; 1.0017x over previous
#include <cuda_runtime.h>
#include <cuda_fp16.h>
#include <math.h>
#include <stdint.h>

#define T_TOK   1024
#define DMODEL  768
#define NEXP    16
#define FFN     3072
#define TOPK    4
#define NASSIGN (T_TOK*TOPK)

// ---------------- scratch (device globals; no allocations allowed) ----------
__device__ uint16_t g_Xg_h[(size_t)NASSIGN*DMODEL];   // gathered activations, fp16
__device__ uint16_t g_act_h[(size_t)NASSIGN*FFN];     // silu(gate)*up, fp16
__device__ uint16_t g_down_h[(size_t)NASSIGN*DMODEL]; // down-proj rows (fp16)
__device__ int      g_topk_idx[T_TOK*TOPK];
__device__ float    g_topk_w[T_TOK*TOPK];
__device__ int      g_off[NEXP+1];
__device__ int      g_assign_token[NASSIGN];
__device__ int      g_token_pos[T_TOK*TOPK];

// ================= helpers =================
__device__ __forceinline__ uint32_t smem_u32(const void* p) {
    uint32_t a;
    asm("{ .reg .u64 t; cvta.to.shared.u64 t, %1; cvt.u32.u64 %0, t; }" : "=r"(a) : "l"(p));
    return a;
}
__device__ __forceinline__ uint32_t pack_h2(float x, float y) {
    uint32_t h;
    asm("cvt.rn.f16x2.f32 %0, %1, %2;" : "=r"(h) : "f"(y), "f"(x));
    return h;
}
__device__ __forceinline__ float2 unpack_h2(uint32_t h) {
    float lo, hi;
    asm("{ .reg .b16 a, b;\n\t mov.b32 {a, b}, %2;\n\t cvt.f32.f16 %0, a;\n\t cvt.f32.f16 %1, b; }"
        : "=f"(lo), "=f"(hi) : "r"(h));
    return make_float2(lo, hi);
}

#define LDSM_X4(r, addr) \
    asm volatile("ldmatrix.sync.aligned.m8n8.x4.shared.b16 {%0,%1,%2,%3}, [%4];" \
        : "=r"((r)[0]),"=r"((r)[1]),"=r"((r)[2]),"=r"((r)[3]) : "r"(addr))

#define MMA_F16(d, a, b0, b1) \
    asm volatile("mma.sync.aligned.m16n8k16.row.col.f32.f16.f16.f32 " \
        "{%0,%1,%2,%3},{%4,%5,%6,%7},{%8,%9},{%0,%1,%2,%3};" \
        : "+f"((d)[0]),"+f"((d)[1]),"+f"((d)[2]),"+f"((d)[3]) \
        : "r"((a)[0]),"r"((a)[1]),"r"((a)[2]),"r"((a)[3]),"r"(b0),"r"(b1))

#define CPA16(dst, src, sz) \
    asm volatile("cp.async.cg.shared.global [%0], [%1], 16, %2;" :: "r"(dst), "l"(src), "r"(sz) : "memory")
#define CP_COMMIT() asm volatile("cp.async.commit_group;" ::: "memory")
#define CP_WAIT2()  asm volatile("cp.async.wait_group 2;" ::: "memory")

// ---------------- router: logits -> softmax -> top4 -> renorm ---------------
__global__ void moe_router(const float* __restrict__ x, const float* __restrict__ rw) {
    const int t = blockIdx.x;
    __shared__ float sx[DMODEL];
    __shared__ float slog[NEXP];
    const int tid = threadIdx.x;
    const float4* xr = (const float4*)(x + (size_t)t*DMODEL);
    float4* sx4 = (float4*)sx;
    for (int i = tid; i < DMODEL/4; i += 128) sx4[i] = xr[i];
    __syncthreads();

    const int warp = tid >> 5, lane = tid & 31;
    for (int e = warp; e < NEXP; e += 4) {
        const float* w = rw + (size_t)e*DMODEL;
        float s = 0.f;
        for (int k = lane; k < DMODEL; k += 32) s = fmaf(sx[k], w[k], s);
        #pragma unroll
        for (int o = 16; o > 0; o >>= 1) s += __shfl_down_sync(0xffffffffu, s, o);
        if (lane == 0) slog[e] = s;
    }
    __syncthreads();

    if (tid == 0) {
        float m = -1e30f;
        #pragma unroll
        for (int e = 0; e < NEXP; e++) m = fmaxf(m, slog[e]);
        float p[NEXP]; float sum = 0.f;
        #pragma unroll
        for (int e = 0; e < NEXP; e++) { p[e] = __expf(slog[e]-m); sum += p[e]; }
        const float inv = 1.f/sum;
        #pragma unroll
        for (int e = 0; e < NEXP; e++) p[e] *= inv;

        int idx[TOPK]; float wv[TOPK]; float ws = 0.f;
        #pragma unroll
        for (int s2 = 0; s2 < TOPK; s2++) {
            int bi = 0; float bv = -1.f;
            #pragma unroll
            for (int e = 0; e < NEXP; e++) if (p[e] > bv) { bv = p[e]; bi = e; }
            idx[s2] = bi; wv[s2] = bv; ws += bv; p[bi] = -2.f;
        }
        const float invw = 1.f/ws;
        #pragma unroll
        for (int s2 = 0; s2 < TOPK; s2++) {
            g_topk_idx[t*TOPK+s2] = idx[s2];
            g_topk_w[t*TOPK+s2]   = wv[s2]*invw;
        }
    }
}

// ---------------- setup: count + prefix + scatter, one block -----------------
__global__ void moe_setup() {
    __shared__ int sc[NEXP], sf[NEXP], so[NEXP];
    const int tid = threadIdx.x;      // 1024 threads, one per token
    if (tid < NEXP) { sc[tid] = 0; sf[tid] = 0; }
    __syncthreads();
    int es[TOPK];
    #pragma unroll
    for (int s = 0; s < TOPK; s++) {
        es[s] = g_topk_idx[tid*TOPK + s];
        atomicAdd(&sc[es[s]], 1);
    }
    __syncthreads();
    if (tid == 0) {
        int s = 0;
        #pragma unroll
        for (int e = 0; e < NEXP; e++) { so[e] = s; g_off[e] = s; s += sc[e]; }
        g_off[NEXP] = s;
    }
    __syncthreads();
    #pragma unroll
    for (int s = 0; s < TOPK; s++) {
        int e = es[s];
        int p = so[e] + atomicAdd(&sf[e], 1);
        g_assign_token[p]     = tid;
        g_token_pos[tid*TOPK+s] = p;
    }
}

// ---------------- gather + convert to fp16 ----------------------------------
__global__ void moe_gather(const float* __restrict__ x) {
    int id = blockIdx.x*blockDim.x + threadIdx.x;
    int p = id / (DMODEL/4);
    int q = id % (DMODEL/4);
    int t = g_assign_token[p];
    float4 v = ((const float4*)x)[(size_t)t*(DMODEL/4) + q];
    uint2 h;
    h.x = pack_h2(v.x, v.y);
    h.y = pack_h2(v.z, v.w);
    *(uint2*)(g_Xg_h + (size_t)p*DMODEL + q*4) = h;
}

// ===================== GEMM1 (fp16 mma, 4-stage + frag pipeline) =============
// BM=128, B tile = 128 smem rows (64 W1 + 64 V1 interleaved by 16), BK=32.
// SMEM row: 32 fp16 = 64B data + 16B pad = 80B. Stage: A 10240 | B 10240.
// 4 stages = 81920 dynamic; 2 CTAs/SM.
#define G1_STAGE 20480
#define G1_NCH   (DMODEL/32)   // 24

__global__ __launch_bounds__(256, 2) void moe_gemm1_mma(const float* __restrict__ w1,
                                                        const float* __restrict__ v1) {
    const int e    = blockIdx.z;
    const int base = g_off[e];
    const int cnt  = g_off[e+1] - base;
    const int m0   = blockIdx.y * 128;
    if (m0 >= cnt) return;
    const int n0w  = blockIdx.x * 64;

    extern __shared__ char smem[];
    const uint32_t smb = smem_u32(smem);

    const int tid = threadIdx.x, lane = tid & 31, wid = tid >> 5;
    const int wm = wid >> 2, wn = wid & 3;     // 2 x 4 warp grid; warp tile 64x32

    // ---- A via cp.async (fp16) ----
    const int crow  = tid >> 1;                 // 0..127
    const int cpair = tid & 1;
    const uint32_t asz = ((m0 + crow) < cnt) ? 16u : 0u;
    const uint16_t* aH = g_Xg_h + (size_t)(base + m0 + crow)*DMODEL + cpair*16;
    const uint32_t adst = smb + (uint32_t)crow*80 + cpair*32;

    // ---- B: fp32 LDG + fp16 cvt + STS (rows 0-63 W1, 64-127 V1 by 16) ----
    const int brow  = tid >> 1;
    const int bhalf = tid & 1;
    const int grp   = brow >> 5, wi = brow & 31;
    const float* bsrc = (wi < 16)
        ? (w1 + (size_t)e*FFN*DMODEL + (size_t)(n0w + grp*16 + wi)*DMODEL)
        : (v1 + (size_t)e*FFN*DMODEL + (size_t)(n0w + grp*16 + (wi-16))*DMODEL);
    const float* bptr = bsrc + bhalf*16;
    const uint32_t boff = (uint32_t)brow*80 + bhalf*32;

    const int rl = (lane & 7) + ((lane >> 3) & 1) * 8;
    const int kl = (lane >> 4) * 16;

    float acc[4][4][4];
    #pragma unroll
    for (int i = 0; i < 4; i++)
        #pragma unroll
        for (int j = 0; j < 4; j++)
            #pragma unroll
            for (int r = 0; r < 4; r++) acc[i][j][r] = 0.f;

    float4 b4[4];

    #define G1_CPA(c) do { \
        if ((c) < G1_NCH) { \
            const uint32_t d = adst + ((c)&3)*G1_STAGE; \
            CPA16(d,      aH + (size_t)(c)*32,     asz); \
            CPA16(d + 16, aH + (size_t)(c)*32 + 8, asz); \
        } \
        CP_COMMIT(); \
    } while (0)

    #define G1_LDGB(c) do { \
        const float4* bp = (const float4*)(bptr + (size_t)(c)*32); \
        b4[0]=bp[0]; b4[1]=bp[1]; b4[2]=bp[2]; b4[3]=bp[3]; \
    } while (0)

    #define G1_STSB(c) do { \
        char* s_ = smem + ((c)&3)*G1_STAGE + 10240; \
        uint4 h; \
        h.x = pack_h2(b4[0].x, b4[0].y); h.y = pack_h2(b4[0].z, b4[0].w); \
        h.z = pack_h2(b4[1].x, b4[1].y); h.w = pack_h2(b4[1].z, b4[1].w); \
        *(uint4*)(s_ + boff) = h; \
        h.x = pack_h2(b4[2].x, b4[2].y); h.y = pack_h2(b4[2].z, b4[2].w); \
        h.z = pack_h2(b4[3].x, b4[3].y); h.w = pack_h2(b4[3].z, b4[3].w); \
        *(uint4*)(s_ + boff + 16) = h; \
    } while (0)

    // ---- prologue: A 0..2 in flight, B0 staged, B1 in regs ----
    G1_CPA(0);
    G1_CPA(1);
    G1_CPA(2);
    G1_LDGB(0);  G1_STSB(0);
    G1_LDGB(1);
    CP_WAIT2();                // A0 landed (A1, A2 may be in flight)
    __syncthreads();

    for (int c = 0; c < G1_NCH; c++) {
        const uint32_t sA = smb + (c&3)*G1_STAGE;
        const uint32_t sB = sA + 10240;
        G1_CPA(c + 3);         // prefetch A three chunks ahead

        uint32_t bh[2][4];
        uint32_t ah[2][4];

        #pragma unroll
        for (int s16 = 0; s16 < 2; s16++) {
            const int kb = s16*32 + kl;
            // B frags for this s16
            #pragma unroll
            for (int jt = 0; jt < 2; jt++) {
                const uint32_t ba = (uint32_t)(wn*32 + jt*16 + rl)*80 + kb;
                LDSM_X4(bh[jt], sB + ba);
            }
            // A frag pipeline across i
            LDSM_X4(ah[0], sA + (uint32_t)(wm*64 + rl)*80 + kb);
            #pragma unroll
            for (int i = 0; i < 4; i++) {
                const int p = i & 1;
                if (i < 3)
                    LDSM_X4(ah[p ^ 1], sA + (uint32_t)(wm*64 + (i+1)*16 + rl)*80 + kb);
                #pragma unroll
                for (int jn = 0; jn < 4; jn++) {
                    const int jt = jn >> 1, hf = jn & 1;
                    MMA_F16(acc[i][jn], ah[p], bh[jt][hf], bh[jt][hf+2]);
                }
                if (s16 == 0) {
                    if (i == 1 && (c + 1 < G1_NCH)) G1_STSB(c + 1);
                    if (i == 2 && (c + 2 < G1_NCH)) G1_LDGB(c + 2);
                }
            }
        }

        if (c + 1 < G1_NCH) {
            CP_WAIT2();        // A(c+1) landed; A(c+2), A(c+3) may be in flight
            __syncthreads();
        }
    }

    // ---- epilogue: silu(gate)*up -> fp16 ----
    const int r0 = lane >> 2;
    const int cq = (lane & 3) * 2;
    #pragma unroll
    for (int i = 0; i < 4; i++) {
        const int mb = m0 + wm*64 + i*16;
        #pragma unroll
        for (int rg = 0; rg < 2; rg++) {
            const int m = mb + rg*8 + r0;
            if (m < cnt) {
                const size_t rowb = (size_t)(base + m)*FFN;
                #pragma unroll
                for (int jj = 0; jj < 2; jj++) {
                    const int cc = n0w + wn*16 + jj*8 + cq;
                    float g0 = acc[i][jj][rg*2+0], g1 = acc[i][jj][rg*2+1];
                    float u0 = acc[i][jj+2][rg*2+0], u1 = acc[i][jj+2][rg*2+1];
                    float o0 = g0/(1.f+__expf(-g0))*u0;
                    float o1 = g1/(1.f+__expf(-g1))*u1;
                    *(uint32_t*)(g_act_h + rowb + cc) = pack_h2(o0, o1);
                }
            }
        }
    }
    #undef G1_CPA
    #undef G1_LDGB
    #undef G1_STSB
}

// ===================== GEMM2 (fp16 mma, BN=128, 4-stage + frag pipeline) =====
// BM=128, BN=128 (128 W2 rows), BK=32. Same geometry as GEMM1.
// Stage: A 10240 | B 10240 = 20480; 4 stages = 81920; 2 CTAs/SM.
#define G2_STAGE 20480
#define G2_NCH   (FFN/32)   // 96

__global__ __launch_bounds__(256, 2) void moe_gemm2_mma(const float* __restrict__ w2) {
    const int e    = blockIdx.z;
    const int base = g_off[e];
    const int cnt  = g_off[e+1] - base;
    const int m0   = blockIdx.y * 128;
    if (m0 >= cnt) return;
    const int n0   = blockIdx.x * 128;

    extern __shared__ char smem[];
    const uint32_t smb = smem_u32(smem);

    const int tid = threadIdx.x, lane = tid & 31, wid = tid >> 5;
    const int wm = wid >> 2, wn = wid & 3;     // 2 x 4 warp grid; warp tile 64x32

    // ---- A via cp.async (fp16 act) ----
    const int crow  = tid >> 1;
    const int cpair = tid & 1;
    const uint32_t asz = ((m0 + crow) < cnt) ? 16u : 0u;
    const uint16_t* aH = g_act_h + (size_t)(base + m0 + crow)*FFN + cpair*16;
    const uint32_t adst = smb + (uint32_t)crow*80 + cpair*32;

    // ---- B: 128 W2 rows, 2 threads per row ----
    const int brow  = tid >> 1;                 // 0..127
    const int bhalf = tid & 1;
    const float* bptr = w2 + (size_t)e*DMODEL*FFN + (size_t)(n0 + brow)*FFN + bhalf*16;
    const uint32_t boff = (uint32_t)brow*80 + bhalf*32;

    const int rl = (lane & 7) + ((lane >> 3) & 1) * 8;
    const int kl = (lane >> 4) * 16;

    float acc[4][4][4];
    #pragma unroll
    for (int i = 0; i < 4; i++)
        #pragma unroll
        for (int j = 0; j < 4; j++)
            #pragma unroll
            for (int r = 0; r < 4; r++) acc[i][j][r] = 0.f;

    float4 b4[4];

    #define G2_CPA(c) do { \
        if ((c) < G2_NCH) { \
            const uint32_t d = adst + ((c)&3)*G2_STAGE; \
            CPA16(d,      aH + (size_t)(c)*32,     asz); \
            CPA16(d + 16, aH + (size_t)(c)*32 + 8, asz); \
        } \
        CP_COMMIT(); \
    } while (0)

    #define G2_LDGB(c) do { \
        const float4* bp = (const float4*)(bptr + (size_t)(c)*32); \
        b4[0]=bp[0]; b4[1]=bp[1]; b4[2]=bp[2]; b4[3]=bp[3]; \
    } while (0)

    #define G2_STSB(c) do { \
        char* s_ = smem + ((c)&3)*G2_STAGE + 10240; \
        uint4 h; \
        h.x = pack_h2(b4[0].x, b4[0].y); h.y = pack_h2(b4[0].z, b4[0].w); \
        h.z = pack_h2(b4[1].x, b4[1].y); h.w = pack_h2(b4[1].z, b4[1].w); \
        *(uint4*)(s_ + boff) = h; \
        h.x = pack_h2(b4[2].x, b4[2].y); h.y = pack_h2(b4[2].z, b4[2].w); \
        h.z = pack_h2(b4[3].x, b4[3].y); h.w = pack_h2(b4[3].z, b4[3].w); \
        *(uint4*)(s_ + boff + 16) = h; \
    } while (0)

    // ---- prologue ----
    G2_CPA(0);
    G2_CPA(1);
    G2_CPA(2);
    G2_LDGB(0);  G2_STSB(0);
    G2_LDGB(1);
    CP_WAIT2();
    __syncthreads();

    for (int c = 0; c < G2_NCH; c++) {
        const uint32_t sA = smb + (c&3)*G2_STAGE;
        const uint32_t sB = sA + 10240;
        G2_CPA(c + 3);

        uint32_t bh[2][4];
        uint32_t ah[2][4];

        #pragma unroll
        for (int s16 = 0; s16 < 2; s16++) {
            const int kb = s16*32 + kl;
            #pragma unroll
            for (int jt = 0; jt < 2; jt++) {
                const uint32_t ba = (uint32_t)(wn*32 + jt*16 + rl)*80 + kb;
                LDSM_X4(bh[jt], sB + ba);
            }
            LDSM_X4(ah[0], sA + (uint32_t)(wm*64 + rl)*80 + kb);
            #pragma unroll
            for (int i = 0; i < 4; i++) {
                const int p = i & 1;
                if (i < 3)
                    LDSM_X4(ah[p ^ 1], sA + (uint32_t)(wm*64 + (i+1)*16 + rl)*80 + kb);
                #pragma unroll
                for (int jn = 0; jn < 4; jn++) {
                    const int jt = jn >> 1, hf = jn & 1;
                    MMA_F16(acc[i][jn], ah[p], bh[jt][hf], bh[jt][hf+2]);
                }
                if (s16 == 0) {
                    if (i == 1 && (c + 1 < G2_NCH)) G2_STSB(c + 1);
                    if (i == 2 && (c + 2 < G2_NCH)) G2_LDGB(c + 2);
                }
            }
        }

        if (c + 1 < G2_NCH) {
            CP_WAIT2();
            __syncthreads();
        }
    }

    // ---- epilogue: fp16 rows of g_down_h ----
    const int r0 = lane >> 2;
    const int cq = (lane & 3) * 2;
    #pragma unroll
    for (int i = 0; i < 4; i++) {
        const int mb = m0 + wm*64 + i*16;
        #pragma unroll
        for (int rg = 0; rg < 2; rg++) {
            const int m = mb + rg*8 + r0;
            if (m < cnt) {
                uint16_t* orow = g_down_h + (size_t)(base + m)*DMODEL;
                #pragma unroll
                for (int jn = 0; jn < 4; jn++) {
                    const int cc = n0 + wn*32 + jn*8 + cq;
                    *(uint32_t*)(orow + cc) = pack_h2(acc[i][jn][rg*2+0], acc[i][jn][rg*2+1]);
                }
            }
        }
    }
    #undef G2_CPA
    #undef G2_LDGB
    #undef G2_STSB
}

// ---------------- combine: out[t] = sum_slot w * down[pos(t,slot)] ----------
__global__ void moe_combine(float* __restrict__ out) {
    int id = blockIdx.x*blockDim.x + threadIdx.x;
    int t = id / (DMODEL/4);
    int q = id % (DMODEL/4);
    float4 acc = make_float4(0,0,0,0);
    #pragma unroll
    for (int s = 0; s < TOPK; s++) {
        int   p = g_token_pos[t*TOPK+s];
        float w = g_topk_w[t*TOPK+s];
        uint2 hv = *(const uint2*)(g_down_h + (size_t)p*DMODEL + q*4);
        float2 v0 = unpack_h2(hv.x);
        float2 v1 = unpack_h2(hv.y);
        acc.x = fmaf(w, v0.x, acc.x);
        acc.y = fmaf(w, v0.y, acc.y);
        acc.z = fmaf(w, v1.x, acc.z);
        acc.w = fmaf(w, v1.y, acc.w);
    }
    ((float4*)out)[id] = acc;
}

// ---------------- launch ----------------------------------------------------
extern "C" void kernel_launch(void* const* d_in, const int* in_sizes, int n_in,
                              void* d_out, int out_size) {
    const float* x  = (const float*)d_in[0];
    const float* rw = (const float*)d_in[1];
    const float* w1 = (const float*)d_in[2];
    const float* v1 = (const float*)d_in[3];
    const float* w2 = (const float*)d_in[4];
    float* out = (float*)d_out;

    cudaFuncSetAttribute(moe_gemm1_mma, cudaFuncAttributeMaxDynamicSharedMemorySize, 4*G1_STAGE);
    cudaFuncSetAttribute(moe_gemm2_mma, cudaFuncAttributeMaxDynamicSharedMemorySize, 4*G2_STAGE);

    moe_router<<<T_TOK, 128>>>(x, rw);                // launch 1
    moe_setup<<<1, 1024>>>();                         // launch 2
    moe_gather<<<(NASSIGN*(DMODEL/4))/256, 256>>>(x); // launch 3

    dim3 g1(FFN/64, NASSIGN/128, NEXP);               // launch 4 <- profiled slot
    moe_gemm1_mma<<<g1, 256, 4*G1_STAGE>>>(w1, v1);

    dim3 g2(DMODEL/128, NASSIGN/128, NEXP);           // 6 x 32 x 16
    moe_gemm2_mma<<<g2, 256, 4*G2_STAGE>>>(w2);

    moe_combine<<<(T_TOK*(DMODEL/4))/256, 256>>>(out);
}